// round 7
// baseline (speedup 1.0000x reference)
#include <cuda_runtime.h>
#include <cuda_fp16.h>
#include <math.h>
#include <stdint.h>

// ---------------------------------------------------------------------------
// GCGRU encoder-decoder. FP16 legacy tensor cores (mma.m16n8k16, fp32 accum),
// ldmatrix fragment loads, 4-stage cp.async pipelines (1 barrier/iter).
//
// Layouts (all half):
//   g_X*  : (N, din_p, B)        stage-1 input, pad cols zero
//   g_Y*  : (slot, N, din_p, B)  stage-1 output for supports {1,2,4,5};
//                                identity supports (0,3) read from g_X.
//   g_Gt  : (slot, N, N)         4 non-identity supports
//   g_Wp  : padded (K*din_p, outd) weights
// ---------------------------------------------------------------------------

#define N_    1024
#define B_    64
#define T_    12
#define HOR_  12
#define C_    2
#define H_    64
#define K_    6

#define NBH_  (N_ * B_ * H_)
#define M_    (N_ * B_)

#define DINR0 66
#define DINP0 80
#define DINR1 128
#define DINP1 128

// ------------------------- scratch (device globals) -------------------------
__device__ float  g_xT[T_ * N_ * B_ * C_];
__device__ float  g_seq[T_ * N_ * B_ * H_];
__device__ float  g_hA[NBH_];
__device__ float  g_hB[NBH_];
__device__ __half g_X0[N_ * DINP0 * B_];
__device__ __half g_X1[N_ * DINP1 * B_];
__device__ __half g_Y0[4ll * N_ * DINP0 * B_];
__device__ __half g_Y1[4ll * N_ * DINP1 * B_];
__device__ float  g_zr[(size_t)M_ * 2 * H_];
__device__ float  g_y[M_ * C_];
__device__ __half g_Gt[4 * N_ * N_];
__device__ __half g_Wp[479232];

// ------------------------------ helpers -------------------------------------
__device__ __forceinline__ void mma_f16(float* c, const uint32_t* a,
                                        const uint32_t* b) {
    asm volatile(
        "mma.sync.aligned.m16n8k16.row.col.f32.f16.f16.f32 "
        "{%0,%1,%2,%3}, {%4,%5,%6,%7}, {%8,%9}, {%0,%1,%2,%3};\n"
        : "+f"(c[0]), "+f"(c[1]), "+f"(c[2]), "+f"(c[3])
        : "r"(a[0]), "r"(a[1]), "r"(a[2]), "r"(a[3]), "r"(b[0]), "r"(b[1]));
}

__device__ __forceinline__ void ldmx4(uint32_t* r, const void* p) {
    uint32_t a = (uint32_t)__cvta_generic_to_shared(p);
    asm volatile("ldmatrix.sync.aligned.m8n8.x4.shared.b16 {%0,%1,%2,%3}, [%4];"
                 : "=r"(r[0]), "=r"(r[1]), "=r"(r[2]), "=r"(r[3]) : "r"(a));
}
__device__ __forceinline__ void ldmx4t(uint32_t* r, const void* p) {
    uint32_t a = (uint32_t)__cvta_generic_to_shared(p);
    asm volatile("ldmatrix.sync.aligned.m8n8.x4.trans.shared.b16 {%0,%1,%2,%3}, [%4];"
                 : "=r"(r[0]), "=r"(r[1]), "=r"(r[2]), "=r"(r[3]) : "r"(a));
}

__device__ __forceinline__ void cp16(void* dst, const void* src) {
    uint32_t d = (uint32_t)__cvta_generic_to_shared(dst);
    asm volatile("cp.async.ca.shared.global [%0], [%1], 16;\n"
                 :: "r"(d), "l"(src));
}
__device__ __forceinline__ void cp_commit() {
    asm volatile("cp.async.commit_group;\n");
}
template <int n>
__device__ __forceinline__ void cp_wait() {
    asm volatile("cp.async.wait_group %0;\n" :: "n"(n));
}

// ------------------------------ prep kernels --------------------------------

__global__ void k_prep_G(const float* __restrict__ G) {
    int idx = blockIdx.x * blockDim.x + threadIdx.x;
    if (idx >= 4 * N_ * N_) return;
    int s = idx / (N_ * N_);
    int r = idx - s * (N_ * N_);
    int kidx = s + 1 + (s >> 1);   // {1,2,4,5}
    g_Gt[idx] = __float2half_rn(G[(size_t)kidx * N_ * N_ + r]);
}

__global__ void k_prep_W(const float* __restrict__ src, __half* __restrict__ dst,
                         int din_r, int din_p, int outd) {
    int idx = blockIdx.x * blockDim.x + threadIdx.x;
    int total = K_ * din_p * outd;
    if (idx >= total) return;
    int o = idx % outd;
    int row = idx / outd;
    int k = row / din_p;
    int f = row - k * din_p;
    dst[idx] = (f < din_r) ? __float2half_rn(src[(size_t)(k * din_r + f) * outd + o])
                           : __float2half_rn(0.f);
}

// ------------------------------ data movement -------------------------------

// x (B,T,N,C) -> g_xT (T,N,B,C)
__global__ void k_transpose_x(const float* __restrict__ x) {
    int idx = blockIdx.x * blockDim.x + threadIdx.x;
    const int total = B_ * T_ * N_ * C_;
    if (idx >= total) return;
    int c = idx % C_;
    int i = (idx / C_) % N_;
    int t = (idx / (C_ * N_)) % T_;
    int b = idx / (C_ * N_ * T_);
    g_xT[(((size_t)t * N_ + i) * B_ + b) * C_ + c] = x[idx];
}

// Gate-pass concat: X[i][f][b] = concat(x,h), f < din_r, fp16-rounded.
__global__ void k_concat_full(const float* __restrict__ xin, int dinx,
                              const float* __restrict__ h,
                              __half* __restrict__ X, int din_r, int din_p) {
    int idx = blockIdx.x * blockDim.x + threadIdx.x;
    int total = N_ * din_r * B_;
    if (idx >= total) return;
    int b = idx & 63;
    int f = (idx >> 6) % din_r;
    int i = idx / (64 * din_r);
    int m = i * B_ + b;
    float v;
    if (f < dinx) v = xin[(size_t)m * dinx + f];
    else          v = h ? h[(size_t)m * H_ + (f - dinx)] : 0.f;
    X[((size_t)i * din_p + f) * B_ + b] = __float2half_rn(v);
}

// Candidate-pass concat: overwrite h-part with r*h.
__global__ void k_concat_h(const float* __restrict__ h, int dinx,
                           __half* __restrict__ X, int din_p) {
    int idx = blockIdx.x * blockDim.x + threadIdx.x;
    int total = N_ * H_ * B_;
    if (idx >= total) return;
    int b = idx & 63;
    int j = (idx >> 6) & 63;
    int i = idx >> 12;
    int m = i * B_ + b;
    float v = 0.f;
    if (h) v = h[(size_t)m * H_ + j] * g_zr[(size_t)m * (2 * H_) + H_ + j];
    X[((size_t)i * din_p + (dinx + j)) * B_ + b] = __float2half_rn(v);
}

// ------------------------------ stage-1 GEMM --------------------------------
// Y[s] = G[s] @ X over columns [col_off, col_off + gridX*128).
// BM=128, BN=128, BK=32, 8 warps (4x2), warp tile 32x64, fp16 mma m16n8k16.
// 4-stage cp.async pipeline, one __syncthreads per iteration.
#define G1_AS_BYTES (128 * 40 * 2)     // 10240 per stage
#define G1_BS_BYTES (32 * 136 * 2)     // 8704 per stage
#define G1_SMEM (4 * (G1_AS_BYTES + G1_BS_BYTES))   // 75776

__global__ __launch_bounds__(256)
void k_gemm1(const __half* __restrict__ Gt, const __half* __restrict__ X,
             __half* __restrict__ Y, int col_off, int ldp) {
    extern __shared__ __align__(16) char dsm[];
    __half (*As)[128][40] = reinterpret_cast<__half(*)[128][40]>(dsm);
    __half (*Bs)[32][136] = reinterpret_cast<__half(*)[32][136]>(dsm + 4 * G1_AS_BYTES);

    const int s = blockIdx.z;
    const __half* A = Gt + (size_t)s * N_ * N_;
    const int m0 = blockIdx.y * 128;
    const int n0 = col_off + blockIdx.x * 128;
    const int tid = threadIdx.x;
    const int lane = tid & 31;
    const int warp = tid >> 5;
    const int wm = (warp & 3) * 32;
    const int wn = (warp >> 2) * 64;
    const int gq = lane >> 2;
    const int t4 = lane & 3;

    float acc[2][8][4];
#pragma unroll
    for (int i = 0; i < 2; i++)
#pragma unroll
        for (int j = 0; j < 8; j++)
#pragma unroll
            for (int l = 0; l < 4; l++) acc[i][j][l] = 0.f;

    auto load_stage = [&](int buf, int kt) {
        int kk0 = kt * 32;
#pragma unroll
        for (int i = 0; i < 2; i++) {
            int idx = tid + i * 256;
            int row = idx >> 2;
            int seg = (idx & 3) << 3;
            cp16(&As[buf][row][seg], A + (size_t)(m0 + row) * N_ + kk0 + seg);
        }
#pragma unroll
        for (int i = 0; i < 2; i++) {
            int idx = tid + i * 256;
            int r = idx >> 4;
            int seg = (idx & 15) << 3;
            cp16(&Bs[buf][r][seg], X + (size_t)(kk0 + r) * ldp + n0 + seg);
        }
    };

    const int KSTEPS = N_ / 32;   // 32
#pragma unroll
    for (int st = 0; st < 3; st++) { load_stage(st, st); cp_commit(); }

    for (int kt = 0; kt < KSTEPS; kt++) {
        const int buf = kt & 3;
        cp_wait<2>();
        __syncthreads();
        if (kt + 3 < KSTEPS) load_stage((kt + 3) & 3, kt + 3);
        cp_commit();   // uniform group count (dummy in tail)

#pragma unroll
        for (int ks = 0; ks < 2; ks++) {
            const int kb = ks * 16;
            uint32_t a[2][4], b[8][2];
#pragma unroll
            for (int mt = 0; mt < 2; mt++) {
                ldmx4(a[mt], &As[buf][wm + mt * 16 + (lane & 15)]
                                     [kb + (lane >> 4) * 8]);
            }
#pragma unroll
            for (int p = 0; p < 4; p++) {
                uint32_t r[4];
                ldmx4t(r, &Bs[buf][kb + (lane & 7) + ((lane >> 3) & 1) * 8]
                                  [wn + p * 16 + (lane >> 4) * 8]);
                b[2 * p][0] = r[0]; b[2 * p][1] = r[1];
                b[2 * p + 1][0] = r[2]; b[2 * p + 1][1] = r[3];
            }
#pragma unroll
            for (int mt = 0; mt < 2; mt++)
#pragma unroll
                for (int nt = 0; nt < 8; nt++)
                    mma_f16(acc[mt][nt], a[mt], b[nt]);
        }
    }

    // coalesced half2 stores
#pragma unroll
    for (int mt = 0; mt < 2; mt++) {
        int row = m0 + wm + mt * 16 + gq;
#pragma unroll
        for (int nt = 0; nt < 8; nt++) {
            int xcol = n0 + wn + nt * 8 + t4 * 2;
#pragma unroll
            for (int hh = 0; hh < 2; hh++) {
                int rr = row + hh * 8;
                __half2 v = __floats2half2_rn(acc[mt][nt][hh * 2 + 0],
                                              acc[mt][nt][hh * 2 + 1]);
                *(__half2*)&Y[((size_t)s * N_ + rr) * ldp + xcol] = v;
            }
        }
    }
}

// ------------------------------ stage-2 GEMM --------------------------------
// out = act(A @ W + bias); A rows m=(node,b), cols (k,f) padded.
// A 16-col sub-chunks come from g_X (k=0,3) or g_Y slot (k=1,2,4,5).
// BM=128 (2 nodes), BN=64, BK=32, 8 warps (4x2), warp tile 32x32.
// 4-stage cp.async pipeline. mode 0: sigmoid->g_zr; mode 1: GRU update.
#define G2_AS_BYTES (32 * 136 * 2)     // 8704 per stage
#define G2_BS_BYTES (32 * 72 * 2)      // 4608 per stage
#define G2_SMEM (4 * (G2_AS_BYTES + G2_BS_BYTES))   // 53248

__global__ __launch_bounds__(256)
void k_gemm2(const __half* __restrict__ Xp, const __half* __restrict__ Yp,
             const __half* __restrict__ W, const float* __restrict__ bias,
             int din_p, int outd, int mode,
             const float* __restrict__ hprev, float* __restrict__ hout) {
    extern __shared__ __align__(16) char dsm[];
    __half (*Ask)[32][136] = reinterpret_cast<__half(*)[32][136]>(dsm);
    __half (*Bs)[32][72]   = reinterpret_cast<__half(*)[32][72]>(dsm + 4 * G2_AS_BYTES);

    const int m0 = blockIdx.y * 128;
    const int i0 = m0 >> 6;            // base node (2 nodes per block)
    const int n0 = blockIdx.x * 64;
    const int tid = threadIdx.x;
    const int lane = tid & 31;
    const int warp = tid >> 5;
    const int wm = (warp & 3) * 32;
    const int wn = (warp >> 2) * 32;
    const int gq = lane >> 2;
    const int t4 = lane & 3;
    const int ldp = din_p * B_;

    float acc[2][4][4];
#pragma unroll
    for (int i = 0; i < 2; i++)
#pragma unroll
        for (int j = 0; j < 4; j++)
#pragma unroll
            for (int l = 0; l < 4; l++) acc[i][j][l] = 0.f;

    auto load_stage = [&](int buf, int kt) {
#pragma unroll
        for (int s16 = 0; s16 < 2; s16++) {
            int kk16 = kt * 32 + s16 * 16;
            int k = kk16 / din_p;
            int f0 = kk16 - k * din_p;
            const __half* basep;
            if (k == 0 || k == 3) basep = Xp;
            else basep = Yp + (size_t)((k < 3) ? k - 1 : k - 2) * N_ * ldp;
            int j = tid >> 4;
            int q = tid & 15;
            int node = q >> 3;
            int ch = (q & 7) << 3;
            cp16(&Ask[buf][s16 * 16 + j][node * 64 + ch],
                 basep + ((size_t)(i0 + node) * din_p + f0 + j) * B_ + ch);
        }
        {
            int kk0 = kt * 32;
            int r = tid >> 3;
            int ch = (tid & 7) << 3;
            cp16(&Bs[buf][r][ch], W + (size_t)(kk0 + r) * outd + n0 + ch);
        }
    };

    const int KSTEPS = (K_ * din_p) >> 5;   // 15 or 24
#pragma unroll
    for (int st = 0; st < 3; st++) { load_stage(st, st); cp_commit(); }

    for (int kt = 0; kt < KSTEPS; kt++) {
        const int buf = kt & 3;
        cp_wait<2>();
        __syncthreads();
        if (kt + 3 < KSTEPS) load_stage((kt + 3) & 3, kt + 3);
        cp_commit();

#pragma unroll
        for (int ks = 0; ks < 2; ks++) {
            const int kb = ks * 16;
            uint32_t a[2][4], b[4][2];
#pragma unroll
            for (int mt = 0; mt < 2; mt++) {
                ldmx4t(a[mt], &Ask[buf][kb + (lane & 7) + ((lane >> 4) & 1) * 8]
                                       [wm + mt * 16 + ((lane >> 3) & 1) * 8]);
            }
#pragma unroll
            for (int p = 0; p < 2; p++) {
                uint32_t r[4];
                ldmx4t(r, &Bs[buf][kb + (lane & 7) + ((lane >> 3) & 1) * 8]
                                  [wn + p * 16 + (lane >> 4) * 8]);
                b[2 * p][0] = r[0]; b[2 * p][1] = r[1];
                b[2 * p + 1][0] = r[2]; b[2 * p + 1][1] = r[3];
            }
#pragma unroll
            for (int mt = 0; mt < 2; mt++)
#pragma unroll
                for (int nt = 0; nt < 4; nt++)
                    mma_f16(acc[mt][nt], a[mt], b[nt]);
        }
    }

#pragma unroll
    for (int mt = 0; mt < 2; mt++) {
        int row = m0 + wm + mt * 16 + gq;
#pragma unroll
        for (int nt = 0; nt < 4; nt++) {
            int nb = n0 + wn + nt * 8 + t4 * 2;
#pragma unroll
            for (int hh = 0; hh < 2; hh++) {
                size_t m = (size_t)(row + hh * 8);
#pragma unroll
                for (int cc = 0; cc < 2; cc++) {
                    int n = nb + cc;
                    float v = acc[mt][nt][hh * 2 + cc] + bias[n];
                    if (mode == 0) {
                        g_zr[m * (2 * H_) + n] = 1.f / (1.f + expf(-v));
                    } else {
                        float z = g_zr[m * (2 * H_) + n];
                        float hold = hprev ? hprev[m * H_ + n] : 0.f;
                        hout[m * H_ + n] = z * tanhf(v) + (1.f - z) * hold;
                    }
                }
            }
        }
    }
}

// Projection + output scatter + decoder feedback.
__global__ void k_proj(const float* __restrict__ projW,
                       const float* __restrict__ projb,
                       int t, float* __restrict__ out) {
    int m = blockIdx.x * blockDim.x + threadIdx.x;
    if (m >= M_) return;
    int i = m / B_;
    int b = m - i * B_;
    float a0 = projb[0], a1 = projb[1];
    const float* hv = &g_hB[(size_t)m * H_];
#pragma unroll
    for (int j = 0; j < H_; j++) {
        float h = hv[j];
        a0 += h * projW[j * 2 + 0];
        a1 += h * projW[j * 2 + 1];
    }
    g_y[(size_t)m * C_ + 0] = a0;
    g_y[(size_t)m * C_ + 1] = a1;
    size_t o = ((((size_t)b * HOR_ + t) * N_) + i) * C_;
    out[o + 0] = a0;
    out[o + 1] = a1;
}

// ------------------------------ host side -----------------------------------

static inline int cdiv(int a, int b) { return (a + b - 1) / b; }

// padded weight offsets inside g_Wp (element counts)
#define OFF_E0G 0
#define OFF_E0U 61440
#define OFF_D0G 92160
#define OFF_D0U 153600
#define OFF_E1G 184320
#define OFF_E1U 282624
#define OFF_D1G 331776
#define OFF_D1U 430080

static void run_cell(const __half* Gt,
                     const float* xin, int dinx,
                     const float* hprev, float* hout,
                     const __half* Wg, const float* bg,
                     const __half* Wu, const float* bu,
                     __half* Xp, __half* Yp, int din_r, int din_p) {
    const int ldp = din_p * B_;

    // gate pass
    k_concat_full<<<cdiv(N_ * din_r * B_, 256), 256>>>(xin, dinx, hprev,
                                                       Xp, din_r, din_p);
    dim3 g1((din_r * B_) / 128, N_ / 128, 4);
    k_gemm1<<<g1, 256, G1_SMEM>>>(Gt, Xp, Yp, 0, ldp);
    k_gemm2<<<dim3(2, M_ / 128), 256, G2_SMEM>>>(Xp, Yp, Wg, bg, din_p,
                                                 2 * H_, 0, nullptr, nullptr);

    // candidate pass: only h columns recomputed
    k_concat_h<<<cdiv(N_ * H_ * B_, 256), 256>>>(hprev, dinx, Xp, din_p);
    dim3 g1h((H_ * B_) / 128, N_ / 128, 4);
    k_gemm1<<<g1h, 256, G1_SMEM>>>(Gt, Xp, Yp, dinx * B_, ldp);
    k_gemm2<<<dim3(1, M_ / 128), 256, G2_SMEM>>>(Xp, Yp, Wu, bu, din_p,
                                                 H_, 1, hprev, hout);
}

extern "C" void kernel_launch(void* const* d_in, const int* in_sizes, int n_in,
                              void* d_out, int out_size) {
    (void)in_sizes; (void)n_in; (void)out_size;

    const float* x = (const float*)d_in[0];
    const float* G = (const float*)d_in[1];
    const float* w[16];
    for (int i = 0; i < 16; i++) w[i] = (const float*)d_in[2 + i];
    const float* projW = (const float*)d_in[18];
    const float* projb = (const float*)d_in[19];
    float* out = (float*)d_out;

    cudaFuncSetAttribute(k_gemm1, cudaFuncAttributeMaxDynamicSharedMemorySize,
                         G1_SMEM);
    cudaFuncSetAttribute(k_gemm2, cudaFuncAttributeMaxDynamicSharedMemorySize,
                         G2_SMEM);

    float *p_xT, *p_seq, *p_hA, *p_hB, *p_y;
    __half *p_X0, *p_X1, *p_Y0, *p_Y1, *p_Gt, *p_Wp;
    cudaGetSymbolAddress((void**)&p_xT,  g_xT);
    cudaGetSymbolAddress((void**)&p_seq, g_seq);
    cudaGetSymbolAddress((void**)&p_hA,  g_hA);
    cudaGetSymbolAddress((void**)&p_hB,  g_hB);
    cudaGetSymbolAddress((void**)&p_y,   g_y);
    cudaGetSymbolAddress((void**)&p_X0,  g_X0);
    cudaGetSymbolAddress((void**)&p_X1,  g_X1);
    cudaGetSymbolAddress((void**)&p_Y0,  g_Y0);
    cudaGetSymbolAddress((void**)&p_Y1,  g_Y1);
    cudaGetSymbolAddress((void**)&p_Gt,  g_Gt);
    cudaGetSymbolAddress((void**)&p_Wp,  g_Wp);

    // prep: round G, pad+round weights (all to fp16)
    k_prep_G<<<cdiv(4 * N_ * N_, 256), 256>>>(G);
    k_prep_W<<<cdiv(K_ * DINP0 * 128, 256), 256>>>(w[0],  p_Wp + OFF_E0G, DINR0, DINP0, 128);
    k_prep_W<<<cdiv(K_ * DINP0 *  64, 256), 256>>>(w[2],  p_Wp + OFF_E0U, DINR0, DINP0,  64);
    k_prep_W<<<cdiv(K_ * DINP1 * 128, 256), 256>>>(w[4],  p_Wp + OFF_E1G, DINR1, DINP1, 128);
    k_prep_W<<<cdiv(K_ * DINP1 *  64, 256), 256>>>(w[6],  p_Wp + OFF_E1U, DINR1, DINP1,  64);
    k_prep_W<<<cdiv(K_ * DINP0 * 128, 256), 256>>>(w[8],  p_Wp + OFF_D0G, DINR0, DINP0, 128);
    k_prep_W<<<cdiv(K_ * DINP0 *  64, 256), 256>>>(w[10], p_Wp + OFF_D0U, DINR0, DINP0,  64);
    k_prep_W<<<cdiv(K_ * DINP1 * 128, 256), 256>>>(w[12], p_Wp + OFF_D1G, DINR1, DINP1, 128);
    k_prep_W<<<cdiv(K_ * DINP1 *  64, 256), 256>>>(w[14], p_Wp + OFF_D1U, DINR1, DINP1,  64);

    {
        int total = B_ * T_ * N_ * C_;
        k_transpose_x<<<cdiv(total, 256), 256>>>(x);
    }

    // encoder layer 0 (din 66 -> padded 80)
    for (int t = 0; t < T_; t++) {
        const float* xin   = p_xT + (size_t)t * N_ * B_ * C_;
        const float* hprev = (t == 0) ? nullptr : p_seq + (size_t)(t - 1) * NBH_;
        float* hout        = p_seq + (size_t)t * NBH_;
        run_cell(p_Gt, xin, C_, hprev, hout,
                 p_Wp + OFF_E0G, w[1], p_Wp + OFF_E0U, w[3],
                 p_X0, p_Y0, DINR0, DINP0);
    }

    // encoder layer 1 (din 128)
    for (int t = 0; t < T_; t++) {
        const float* xin   = p_seq + (size_t)t * NBH_;
        const float* hprev = (t == 0) ? nullptr : p_hB;
        run_cell(p_Gt, xin, H_, hprev, p_hB,
                 p_Wp + OFF_E1G, w[5], p_Wp + OFF_E1U, w[7],
                 p_X1, p_Y1, DINR1, DINP1);
    }

    // decoder init
    cudaMemcpyAsync(p_hA, p_seq + (size_t)(T_ - 1) * NBH_,
                    (size_t)NBH_ * sizeof(float), cudaMemcpyDeviceToDevice);
    cudaMemsetAsync(p_y, 0, (size_t)M_ * C_ * sizeof(float));

    // decoder loop
    for (int t = 0; t < HOR_; t++) {
        run_cell(p_Gt, p_y, C_, p_hA, p_hA,
                 p_Wp + OFF_D0G, w[9], p_Wp + OFF_D0U, w[11],
                 p_X0, p_Y0, DINR0, DINP0);
        run_cell(p_Gt, p_hA, H_, p_hB, p_hB,
                 p_Wp + OFF_D1G, w[13], p_Wp + OFF_D1U, w[15],
                 p_X1, p_Y1, DINR1, DINP1);
        k_proj<<<cdiv(M_, 256), 256>>>(projW, projb, t, out);
    }
}

// round 8
// speedup vs baseline: 1.0984x; 1.0984x over previous
#include <cuda_runtime.h>
#include <cuda_fp16.h>
#include <math.h>
#include <stdint.h>

// ---------------------------------------------------------------------------
// GCGRU encoder-decoder. FP16 legacy tensor cores (mma.m16n8k16, fp32 accum),
// ldmatrix fragment loads, 2-stage cp.async double buffering (R5 config —
// best measured). Launches ordered so ncu (-s 5 -c 1) captures k_gemm1.
//
// Layouts (all half):
//   g_X*  : (N, din_p, B)        stage-1 input, pad cols zero
//   g_Y*  : (slot, N, din_p, B)  stage-1 output for supports {1,2,4,5};
//                                identity supports (0,3) read from g_X.
//   g_Gt  : (slot, N, N)         4 non-identity supports
//   g_Wp  : padded (K*din_p, outd) weights
// ---------------------------------------------------------------------------

#define N_    1024
#define B_    64
#define T_    12
#define HOR_  12
#define C_    2
#define H_    64
#define K_    6

#define NBH_  (N_ * B_ * H_)
#define M_    (N_ * B_)

#define DINR0 66
#define DINP0 80
#define DINR1 128
#define DINP1 128

// ------------------------- scratch (device globals) -------------------------
__device__ float  g_xT[T_ * N_ * B_ * C_];
__device__ float  g_seq[T_ * N_ * B_ * H_];
__device__ float  g_hA[NBH_];
__device__ float  g_hB[NBH_];
__device__ __half g_X0[N_ * DINP0 * B_];
__device__ __half g_X1[N_ * DINP1 * B_];
__device__ __half g_Y0[4ll * N_ * DINP0 * B_];
__device__ __half g_Y1[4ll * N_ * DINP1 * B_];
__device__ float  g_zr[(size_t)M_ * 2 * H_];
__device__ float  g_y[M_ * C_];
__device__ __half g_Gt[4 * N_ * N_];
__device__ __half g_Wp[479232];

// ------------------------------ helpers -------------------------------------
__device__ __forceinline__ void mma_f16(float* c, const uint32_t* a,
                                        const uint32_t* b) {
    asm volatile(
        "mma.sync.aligned.m16n8k16.row.col.f32.f16.f16.f32 "
        "{%0,%1,%2,%3}, {%4,%5,%6,%7}, {%8,%9}, {%0,%1,%2,%3};\n"
        : "+f"(c[0]), "+f"(c[1]), "+f"(c[2]), "+f"(c[3])
        : "r"(a[0]), "r"(a[1]), "r"(a[2]), "r"(a[3]), "r"(b[0]), "r"(b[1]));
}

__device__ __forceinline__ void ldmx4(uint32_t* r, const void* p) {
    uint32_t a = (uint32_t)__cvta_generic_to_shared(p);
    asm volatile("ldmatrix.sync.aligned.m8n8.x4.shared.b16 {%0,%1,%2,%3}, [%4];"
                 : "=r"(r[0]), "=r"(r[1]), "=r"(r[2]), "=r"(r[3]) : "r"(a));
}
__device__ __forceinline__ void ldmx4t(uint32_t* r, const void* p) {
    uint32_t a = (uint32_t)__cvta_generic_to_shared(p);
    asm volatile("ldmatrix.sync.aligned.m8n8.x4.trans.shared.b16 {%0,%1,%2,%3}, [%4];"
                 : "=r"(r[0]), "=r"(r[1]), "=r"(r[2]), "=r"(r[3]) : "r"(a));
}

__device__ __forceinline__ void cp16(void* dst, const void* src) {
    uint32_t d = (uint32_t)__cvta_generic_to_shared(dst);
    asm volatile("cp.async.ca.shared.global [%0], [%1], 16;\n"
                 :: "r"(d), "l"(src));
}
// L1-bypass variant for streaming operands (G tiles)
__device__ __forceinline__ void cp16cg(void* dst, const void* src) {
    uint32_t d = (uint32_t)__cvta_generic_to_shared(dst);
    asm volatile("cp.async.cg.shared.global [%0], [%1], 16;\n"
                 :: "r"(d), "l"(src));
}
__device__ __forceinline__ void cp_commit() {
    asm volatile("cp.async.commit_group;\n");
}
template <int n>
__device__ __forceinline__ void cp_wait() {
    asm volatile("cp.async.wait_group %0;\n" :: "n"(n));
}

// ------------------------------ prep kernels --------------------------------

__global__ void k_prep_G(const float* __restrict__ G) {
    int idx = blockIdx.x * blockDim.x + threadIdx.x;
    if (idx >= 4 * N_ * N_) return;
    int s = idx / (N_ * N_);
    int r = idx - s * (N_ * N_);
    int kidx = s + 1 + (s >> 1);   // {1,2,4,5}
    g_Gt[idx] = __float2half_rn(G[(size_t)kidx * N_ * N_ + r]);
}

__global__ void k_prep_W(const float* __restrict__ src, __half* __restrict__ dst,
                         int din_r, int din_p, int outd) {
    int idx = blockIdx.x * blockDim.x + threadIdx.x;
    int total = K_ * din_p * outd;
    if (idx >= total) return;
    int o = idx % outd;
    int row = idx / outd;
    int k = row / din_p;
    int f = row - k * din_p;
    dst[idx] = (f < din_r) ? __float2half_rn(src[(size_t)(k * din_r + f) * outd + o])
                           : __float2half_rn(0.f);
}

// ------------------------------ data movement -------------------------------

// x (B,T,N,C) -> g_xT (T,N,B,C)
__global__ void k_transpose_x(const float* __restrict__ x) {
    int idx = blockIdx.x * blockDim.x + threadIdx.x;
    const int total = B_ * T_ * N_ * C_;
    if (idx >= total) return;
    int c = idx % C_;
    int i = (idx / C_) % N_;
    int t = (idx / (C_ * N_)) % T_;
    int b = idx / (C_ * N_ * T_);
    g_xT[(((size_t)t * N_ + i) * B_ + b) * C_ + c] = x[idx];
}

// Gate-pass concat: X[i][f][b] = concat(x,h), f < din_r, fp16-rounded.
__global__ void k_concat_full(const float* __restrict__ xin, int dinx,
                              const float* __restrict__ h,
                              __half* __restrict__ X, int din_r, int din_p) {
    int idx = blockIdx.x * blockDim.x + threadIdx.x;
    int total = N_ * din_r * B_;
    if (idx >= total) return;
    int b = idx & 63;
    int f = (idx >> 6) % din_r;
    int i = idx / (64 * din_r);
    int m = i * B_ + b;
    float v;
    if (f < dinx) v = xin[(size_t)m * dinx + f];
    else          v = h ? h[(size_t)m * H_ + (f - dinx)] : 0.f;
    X[((size_t)i * din_p + f) * B_ + b] = __float2half_rn(v);
}

// Candidate-pass concat: overwrite h-part with r*h.
__global__ void k_concat_h(const float* __restrict__ h, int dinx,
                           __half* __restrict__ X, int din_p) {
    int idx = blockIdx.x * blockDim.x + threadIdx.x;
    int total = N_ * H_ * B_;
    if (idx >= total) return;
    int b = idx & 63;
    int j = (idx >> 6) & 63;
    int i = idx >> 12;
    int m = i * B_ + b;
    float v = 0.f;
    if (h) v = h[(size_t)m * H_ + j] * g_zr[(size_t)m * (2 * H_) + H_ + j];
    X[((size_t)i * din_p + (dinx + j)) * B_ + b] = __float2half_rn(v);
}

// ------------------------------ stage-1 GEMM --------------------------------
// Y[s] = G[s] @ X over columns [col_off, col_off + gridX*128).
// BM=128, BN=128, BK=32, 8 warps (4x2), warp tile 32x64, fp16 mma m16n8k16.
// 2-stage cp.async double buffering (R5 config).
__global__ __launch_bounds__(256)
void k_gemm1(const __half* __restrict__ Gt, const __half* __restrict__ X,
             __half* __restrict__ Y, int col_off, int ldp) {
    __shared__ __align__(16) __half As[2][128][40];   // BK=32 + pad 8
    __shared__ __align__(16) __half Bs[2][32][136];   // BN=128 + pad 8

    const int s = blockIdx.z;
    const __half* A = Gt + (size_t)s * N_ * N_;
    const int m0 = blockIdx.y * 128;
    const int n0 = col_off + blockIdx.x * 128;
    const int tid = threadIdx.x;
    const int lane = tid & 31;
    const int warp = tid >> 5;
    const int wm = (warp & 3) * 32;
    const int wn = (warp >> 2) * 64;
    const int gq = lane >> 2;
    const int t4 = lane & 3;

    float acc[2][8][4];
#pragma unroll
    for (int i = 0; i < 2; i++)
#pragma unroll
        for (int j = 0; j < 8; j++)
#pragma unroll
            for (int l = 0; l < 4; l++) acc[i][j][l] = 0.f;

    auto load_stage = [&](int buf, int kk0) {
#pragma unroll
        for (int i = 0; i < 2; i++) {
            int idx = tid + i * 256;
            int row = idx >> 2;
            int seg = (idx & 3) << 3;
            cp16cg(&As[buf][row][seg], A + (size_t)(m0 + row) * N_ + kk0 + seg);
        }
#pragma unroll
        for (int i = 0; i < 2; i++) {
            int idx = tid + i * 256;
            int r = idx >> 4;
            int seg = (idx & 15) << 3;
            cp16(&Bs[buf][r][seg], X + (size_t)(kk0 + r) * ldp + n0 + seg);
        }
    };

    load_stage(0, 0);
    cp_commit();

    const int KSTEPS = N_ / 32;
    for (int kt = 0; kt < KSTEPS; kt++) {
        int buf = kt & 1;
        if (kt + 1 < KSTEPS) {
            load_stage(buf ^ 1, (kt + 1) * 32);
            cp_commit();
            cp_wait<1>();
        } else {
            cp_wait<0>();
        }
        __syncthreads();

#pragma unroll
        for (int ks = 0; ks < 2; ks++) {
            const int kb = ks * 16;
            uint32_t a[2][4], b[8][2];
#pragma unroll
            for (int mt = 0; mt < 2; mt++) {
                ldmx4(a[mt], &As[buf][wm + mt * 16 + (lane & 15)]
                                     [kb + (lane >> 4) * 8]);
            }
#pragma unroll
            for (int p = 0; p < 4; p++) {
                uint32_t r[4];
                ldmx4t(r, &Bs[buf][kb + (lane & 7) + ((lane >> 3) & 1) * 8]
                                  [wn + p * 16 + (lane >> 4) * 8]);
                b[2 * p][0] = r[0]; b[2 * p][1] = r[1];
                b[2 * p + 1][0] = r[2]; b[2 * p + 1][1] = r[3];
            }
#pragma unroll
            for (int mt = 0; mt < 2; mt++)
#pragma unroll
                for (int nt = 0; nt < 8; nt++)
                    mma_f16(acc[mt][nt], a[mt], b[nt]);
        }
        __syncthreads();
    }

    // coalesced half2 stores
#pragma unroll
    for (int mt = 0; mt < 2; mt++) {
        int row = m0 + wm + mt * 16 + gq;
#pragma unroll
        for (int nt = 0; nt < 8; nt++) {
            int xcol = n0 + wn + nt * 8 + t4 * 2;
#pragma unroll
            for (int hh = 0; hh < 2; hh++) {
                int rr = row + hh * 8;
                __half2 v = __floats2half2_rn(acc[mt][nt][hh * 2 + 0],
                                              acc[mt][nt][hh * 2 + 1]);
                *(__half2*)&Y[((size_t)s * N_ + rr) * ldp + xcol] = v;
            }
        }
    }
}

// ------------------------------ stage-2 GEMM --------------------------------
// out = act(A @ W + bias); A rows m=(node,b), cols (k,f) padded.
// A 16-col sub-chunks come from g_X (k=0,3) or g_Y slot (k=1,2,4,5).
// BM=128 (2 nodes), BN=64, BK=32, 8 warps (4x2), warp tile 32x32.
// 2-stage cp.async. mode 0: sigmoid->g_zr; mode 1: GRU update.
__global__ __launch_bounds__(256)
void k_gemm2(const __half* __restrict__ Xp, const __half* __restrict__ Yp,
             const __half* __restrict__ W, const float* __restrict__ bias,
             int din_p, int outd, int mode,
             const float* __restrict__ hprev, float* __restrict__ hout) {
    __shared__ __align__(16) __half Ask[2][32][136];
    __shared__ __align__(16) __half Bs[2][32][72];

    const int m0 = blockIdx.y * 128;
    const int i0 = m0 >> 6;            // base node (2 nodes per block)
    const int n0 = blockIdx.x * 64;
    const int tid = threadIdx.x;
    const int lane = tid & 31;
    const int warp = tid >> 5;
    const int wm = (warp & 3) * 32;
    const int wn = (warp >> 2) * 32;
    const int gq = lane >> 2;
    const int t4 = lane & 3;
    const int ldp = din_p * B_;

    float acc[2][4][4];
#pragma unroll
    for (int i = 0; i < 2; i++)
#pragma unroll
        for (int j = 0; j < 4; j++)
#pragma unroll
            for (int l = 0; l < 4; l++) acc[i][j][l] = 0.f;

    auto load_stage = [&](int buf, int kt) {
#pragma unroll
        for (int s16 = 0; s16 < 2; s16++) {
            int kk16 = kt * 32 + s16 * 16;
            int k = kk16 / din_p;
            int f0 = kk16 - k * din_p;
            const __half* basep;
            if (k == 0 || k == 3) basep = Xp;
            else basep = Yp + (size_t)((k < 3) ? k - 1 : k - 2) * N_ * ldp;
            int j = tid >> 4;
            int q = tid & 15;
            int node = q >> 3;
            int ch = (q & 7) << 3;
            cp16(&Ask[buf][s16 * 16 + j][node * 64 + ch],
                 basep + ((size_t)(i0 + node) * din_p + f0 + j) * B_ + ch);
        }
        {
            int kk0 = kt * 32;
            int r = tid >> 3;
            int ch = (tid & 7) << 3;
            cp16(&Bs[buf][r][ch], W + (size_t)(kk0 + r) * outd + n0 + ch);
        }
    };

    load_stage(0, 0);
    cp_commit();

    const int KSTEPS = (K_ * din_p) >> 5;
    for (int kt = 0; kt < KSTEPS; kt++) {
        int buf = kt & 1;
        if (kt + 1 < KSTEPS) {
            load_stage(buf ^ 1, kt + 1);
            cp_commit();
            cp_wait<1>();
        } else {
            cp_wait<0>();
        }
        __syncthreads();

#pragma unroll
        for (int ks = 0; ks < 2; ks++) {
            const int kb = ks * 16;
            uint32_t a[2][4], b[4][2];
#pragma unroll
            for (int mt = 0; mt < 2; mt++) {
                ldmx4t(a[mt], &Ask[buf][kb + (lane & 7) + ((lane >> 4) & 1) * 8]
                                       [wm + mt * 16 + ((lane >> 3) & 1) * 8]);
            }
#pragma unroll
            for (int p = 0; p < 2; p++) {
                uint32_t r[4];
                ldmx4t(r, &Bs[buf][kb + (lane & 7) + ((lane >> 3) & 1) * 8]
                                  [wn + p * 16 + (lane >> 4) * 8]);
                b[2 * p][0] = r[0]; b[2 * p][1] = r[1];
                b[2 * p + 1][0] = r[2]; b[2 * p + 1][1] = r[3];
            }
#pragma unroll
            for (int mt = 0; mt < 2; mt++)
#pragma unroll
                for (int nt = 0; nt < 4; nt++)
                    mma_f16(acc[mt][nt], a[mt], b[nt]);
        }
        __syncthreads();
    }

#pragma unroll
    for (int mt = 0; mt < 2; mt++) {
        int row = m0 + wm + mt * 16 + gq;
#pragma unroll
        for (int nt = 0; nt < 4; nt++) {
            int nb = n0 + wn + nt * 8 + t4 * 2;
#pragma unroll
            for (int hh = 0; hh < 2; hh++) {
                size_t m = (size_t)(row + hh * 8);
#pragma unroll
                for (int cc = 0; cc < 2; cc++) {
                    int n = nb + cc;
                    float v = acc[mt][nt][hh * 2 + cc] + bias[n];
                    if (mode == 0) {
                        g_zr[m * (2 * H_) + n] = 1.f / (1.f + expf(-v));
                    } else {
                        float z = g_zr[m * (2 * H_) + n];
                        float hold = hprev ? hprev[m * H_ + n] : 0.f;
                        hout[m * H_ + n] = z * tanhf(v) + (1.f - z) * hold;
                    }
                }
            }
        }
    }
}

// Projection + output scatter + decoder feedback.
__global__ void k_proj(const float* __restrict__ projW,
                       const float* __restrict__ projb,
                       int t, float* __restrict__ out) {
    int m = blockIdx.x * blockDim.x + threadIdx.x;
    if (m >= M_) return;
    int i = m / B_;
    int b = m - i * B_;
    float a0 = projb[0], a1 = projb[1];
    const float* hv = &g_hB[(size_t)m * H_];
#pragma unroll
    for (int j = 0; j < H_; j++) {
        float h = hv[j];
        a0 += h * projW[j * 2 + 0];
        a1 += h * projW[j * 2 + 1];
    }
    g_y[(size_t)m * C_ + 0] = a0;
    g_y[(size_t)m * C_ + 1] = a1;
    size_t o = ((((size_t)b * HOR_ + t) * N_) + i) * C_;
    out[o + 0] = a0;
    out[o + 1] = a1;
}

// ------------------------------ host side -----------------------------------

static inline int cdiv(int a, int b) { return (a + b - 1) / b; }

// padded weight offsets inside g_Wp (element counts)
#define OFF_E0G 0
#define OFF_E0U 61440
#define OFF_D0G 92160
#define OFF_D0U 153600
#define OFF_E1G 184320
#define OFF_E1U 282624
#define OFF_D1G 331776
#define OFF_D1U 430080

// gate-pass start: concat + stage-1 GEMM
static void cell_gate_start(const __half* Gt, const float* xin, int dinx,
                            const float* hprev, __half* Xp, __half* Yp,
                            int din_r, int din_p) {
    const int ldp = din_p * B_;
    k_concat_full<<<cdiv(N_ * din_r * B_, 256), 256>>>(xin, dinx, hprev,
                                                       Xp, din_r, din_p);
    dim3 g1((din_r * B_) / 128, N_ / 128, 4);
    k_gemm1<<<g1, 256>>>(Gt, Xp, Yp, 0, ldp);
}

// rest of cell: gate gemm2, candidate pass
static void cell_rest(const __half* Gt, int dinx,
                      const float* hprev, float* hout,
                      const __half* Wg, const float* bg,
                      const __half* Wu, const float* bu,
                      __half* Xp, __half* Yp, int din_p) {
    const int ldp = din_p * B_;
    k_gemm2<<<dim3(2, M_ / 128), 256>>>(Xp, Yp, Wg, bg, din_p, 2 * H_, 0,
                                        nullptr, nullptr);
    k_concat_h<<<cdiv(N_ * H_ * B_, 256), 256>>>(hprev, dinx, Xp, din_p);
    dim3 g1h((H_ * B_) / 128, N_ / 128, 4);
    k_gemm1<<<g1h, 256>>>(Gt, Xp, Yp, dinx * B_, ldp);
    k_gemm2<<<dim3(1, M_ / 128), 256>>>(Xp, Yp, Wu, bu, din_p, H_, 1,
                                        hprev, hout);
}

static void run_cell(const __half* Gt, const float* xin, int dinx,
                     const float* hprev, float* hout,
                     const __half* Wg, const float* bg,
                     const __half* Wu, const float* bu,
                     __half* Xp, __half* Yp, int din_r, int din_p) {
    cell_gate_start(Gt, xin, dinx, hprev, Xp, Yp, din_r, din_p);
    cell_rest(Gt, dinx, hprev, hout, Wg, bg, Wu, bu, Xp, Yp, din_p);
}

extern "C" void kernel_launch(void* const* d_in, const int* in_sizes, int n_in,
                              void* d_out, int out_size) {
    (void)in_sizes; (void)n_in; (void)out_size;

    const float* x = (const float*)d_in[0];
    const float* G = (const float*)d_in[1];
    const float* w[16];
    for (int i = 0; i < 16; i++) w[i] = (const float*)d_in[2 + i];
    const float* projW = (const float*)d_in[18];
    const float* projb = (const float*)d_in[19];
    float* out = (float*)d_out;

    float *p_xT, *p_seq, *p_hA, *p_hB, *p_y;
    __half *p_X0, *p_X1, *p_Y0, *p_Y1, *p_Gt, *p_Wp;
    cudaGetSymbolAddress((void**)&p_xT,  g_xT);
    cudaGetSymbolAddress((void**)&p_seq, g_seq);
    cudaGetSymbolAddress((void**)&p_hA,  g_hA);
    cudaGetSymbolAddress((void**)&p_hB,  g_hB);
    cudaGetSymbolAddress((void**)&p_y,   g_y);
    cudaGetSymbolAddress((void**)&p_X0,  g_X0);
    cudaGetSymbolAddress((void**)&p_X1,  g_X1);
    cudaGetSymbolAddress((void**)&p_Y0,  g_Y0);
    cudaGetSymbolAddress((void**)&p_Y1,  g_Y1);
    cudaGetSymbolAddress((void**)&p_Gt,  g_Gt);
    cudaGetSymbolAddress((void**)&p_Wp,  g_Wp);

    // --- launches 1-5: minimal prep so launch #6 is k_gemm1 (ncu target) ---
    k_prep_G<<<cdiv(4 * N_ * N_, 256), 256>>>(G);                       // 1
    {
        int total = B_ * T_ * N_ * C_;
        k_transpose_x<<<cdiv(total, 256), 256>>>(x);                    // 2
    }
    k_prep_W<<<cdiv(K_ * DINP0 * 128, 256), 256>>>(w[0], p_Wp + OFF_E0G,
                                                   DINR0, DINP0, 128);  // 3
    k_prep_W<<<cdiv(K_ * DINP0 *  64, 256), 256>>>(w[2], p_Wp + OFF_E0U,
                                                   DINR0, DINP0,  64);  // 4
    // enc0 t=0 gate pass start (launches 5 = concat, 6 = k_gemm1)
    cell_gate_start(p_Gt, p_xT, C_, nullptr, p_X0, p_Y0, DINR0, DINP0);

    // remaining weight prep (stream-ordered before first use)
    k_prep_W<<<cdiv(K_ * DINP1 * 128, 256), 256>>>(w[4],  p_Wp + OFF_E1G, DINR1, DINP1, 128);
    k_prep_W<<<cdiv(K_ * DINP1 *  64, 256), 256>>>(w[6],  p_Wp + OFF_E1U, DINR1, DINP1,  64);
    k_prep_W<<<cdiv(K_ * DINP0 * 128, 256), 256>>>(w[8],  p_Wp + OFF_D0G, DINR0, DINP0, 128);
    k_prep_W<<<cdiv(K_ * DINP0 *  64, 256), 256>>>(w[10], p_Wp + OFF_D0U, DINR0, DINP0,  64);
    k_prep_W<<<cdiv(K_ * DINP1 * 128, 256), 256>>>(w[12], p_Wp + OFF_D1G, DINR1, DINP1, 128);
    k_prep_W<<<cdiv(K_ * DINP1 *  64, 256), 256>>>(w[14], p_Wp + OFF_D1U, DINR1, DINP1,  64);

    // finish enc0 t=0
    cell_rest(p_Gt, C_, nullptr, p_seq,
              p_Wp + OFF_E0G, w[1], p_Wp + OFF_E0U, w[3],
              p_X0, p_Y0, DINP0);

    // encoder layer 0, t=1..11
    for (int t = 1; t < T_; t++) {
        const float* xin   = p_xT + (size_t)t * N_ * B_ * C_;
        const float* hprev = p_seq + (size_t)(t - 1) * NBH_;
        float* hout        = p_seq + (size_t)t * NBH_;
        run_cell(p_Gt, xin, C_, hprev, hout,
                 p_Wp + OFF_E0G, w[1], p_Wp + OFF_E0U, w[3],
                 p_X0, p_Y0, DINR0, DINP0);
    }

    // encoder layer 1 (din 128)
    for (int t = 0; t < T_; t++) {
        const float* xin   = p_seq + (size_t)t * NBH_;
        const float* hprev = (t == 0) ? nullptr : p_hB;
        run_cell(p_Gt, xin, H_, hprev, p_hB,
                 p_Wp + OFF_E1G, w[5], p_Wp + OFF_E1U, w[7],
                 p_X1, p_Y1, DINR1, DINP1);
    }

    // decoder feedback init (hA copy eliminated: first dec0 reads enc0's
    // last hidden buffer directly and writes into p_hA)
    cudaMemsetAsync(p_y, 0, (size_t)M_ * C_ * sizeof(float));

    // decoder loop
    for (int t = 0; t < HOR_; t++) {
        const float* h0prev = (t == 0) ? (p_seq + (size_t)(T_ - 1) * NBH_)
                                       : p_hA;
        run_cell(p_Gt, p_y, C_, h0prev, p_hA,
                 p_Wp + OFF_D0G, w[9], p_Wp + OFF_D0U, w[11],
                 p_X0, p_Y0, DINR0, DINP0);
        run_cell(p_Gt, p_hA, H_, p_hB, p_hB,
                 p_Wp + OFF_D1G, w[13], p_Wp + OFF_D1U, w[15],
                 p_X1, p_Y1, DINR1, DINP1);
        k_proj<<<cdiv(M_, 256), 256>>>(projW, projb, t, out);
    }
}

// round 10
// speedup vs baseline: 1.1218x; 1.0213x over previous
#include <cuda_runtime.h>
#include <cuda_fp16.h>
#include <math.h>
#include <stdint.h>

// ---------------------------------------------------------------------------
// GCGRU encoder-decoder. FP16 legacy tensor cores (mma.m16n8k16, fp32 accum),
// ldmatrix fragment loads, 2-stage cp.async double buffering.
// R10: gemm1 BK=64 in DYNAMIC smem (71,680 B > 48K static cap);
//      gate-pass gemm2 BN=128 (k_gemm2g).
//
// Layouts (all half):
//   g_X*  : (N, din_p, B)        stage-1 input, pad cols zero
//   g_Y*  : (slot, N, din_p, B)  stage-1 output for supports {1,2,4,5};
//                                identity supports (0,3) read from g_X.
//   g_Gt  : (slot, N, N)         4 non-identity supports
//   g_Wp  : padded (K*din_p, outd) weights
// ---------------------------------------------------------------------------

#define N_    1024
#define B_    64
#define T_    12
#define HOR_  12
#define C_    2
#define H_    64
#define K_    6

#define NBH_  (N_ * B_ * H_)
#define M_    (N_ * B_)

#define DINR0 66
#define DINP0 80
#define DINR1 128
#define DINP1 128

// ------------------------- scratch (device globals) -------------------------
__device__ float  g_xT[T_ * N_ * B_ * C_];
__device__ float  g_seq[T_ * N_ * B_ * H_];
__device__ float  g_hA[NBH_];
__device__ float  g_hB[NBH_];
__device__ __half g_X0[N_ * DINP0 * B_];
__device__ __half g_X1[N_ * DINP1 * B_];
__device__ __half g_Y0[4ll * N_ * DINP0 * B_];
__device__ __half g_Y1[4ll * N_ * DINP1 * B_];
__device__ float  g_zr[(size_t)M_ * 2 * H_];
__device__ float  g_y[M_ * C_];
__device__ __half g_Gt[4 * N_ * N_];
__device__ __half g_Wp[479232];

// ------------------------------ helpers -------------------------------------
__device__ __forceinline__ void mma_f16(float* c, const uint32_t* a,
                                        const uint32_t* b) {
    asm volatile(
        "mma.sync.aligned.m16n8k16.row.col.f32.f16.f16.f32 "
        "{%0,%1,%2,%3}, {%4,%5,%6,%7}, {%8,%9}, {%0,%1,%2,%3};\n"
        : "+f"(c[0]), "+f"(c[1]), "+f"(c[2]), "+f"(c[3])
        : "r"(a[0]), "r"(a[1]), "r"(a[2]), "r"(a[3]), "r"(b[0]), "r"(b[1]));
}

__device__ __forceinline__ void ldmx4(uint32_t* r, const void* p) {
    uint32_t a = (uint32_t)__cvta_generic_to_shared(p);
    asm volatile("ldmatrix.sync.aligned.m8n8.x4.shared.b16 {%0,%1,%2,%3}, [%4];"
                 : "=r"(r[0]), "=r"(r[1]), "=r"(r[2]), "=r"(r[3]) : "r"(a));
}
__device__ __forceinline__ void ldmx4t(uint32_t* r, const void* p) {
    uint32_t a = (uint32_t)__cvta_generic_to_shared(p);
    asm volatile("ldmatrix.sync.aligned.m8n8.x4.trans.shared.b16 {%0,%1,%2,%3}, [%4];"
                 : "=r"(r[0]), "=r"(r[1]), "=r"(r[2]), "=r"(r[3]) : "r"(a));
}

__device__ __forceinline__ void cp16(void* dst, const void* src) {
    uint32_t d = (uint32_t)__cvta_generic_to_shared(dst);
    asm volatile("cp.async.ca.shared.global [%0], [%1], 16;\n"
                 :: "r"(d), "l"(src));
}
// L1-bypass variant for streaming operands (G tiles)
__device__ __forceinline__ void cp16cg(void* dst, const void* src) {
    uint32_t d = (uint32_t)__cvta_generic_to_shared(dst);
    asm volatile("cp.async.cg.shared.global [%0], [%1], 16;\n"
                 :: "r"(d), "l"(src));
}
__device__ __forceinline__ void cp_commit() {
    asm volatile("cp.async.commit_group;\n");
}
template <int n>
__device__ __forceinline__ void cp_wait() {
    asm volatile("cp.async.wait_group %0;\n" :: "n"(n));
}

// ------------------------------ prep kernels --------------------------------

__global__ void k_prep_G(const float* __restrict__ G) {
    int idx = blockIdx.x * blockDim.x + threadIdx.x;
    if (idx >= 4 * N_ * N_) return;
    int s = idx / (N_ * N_);
    int r = idx - s * (N_ * N_);
    int kidx = s + 1 + (s >> 1);   // {1,2,4,5}
    g_Gt[idx] = __float2half_rn(G[(size_t)kidx * N_ * N_ + r]);
}

__global__ void k_prep_W(const float* __restrict__ src, __half* __restrict__ dst,
                         int din_r, int din_p, int outd) {
    int idx = blockIdx.x * blockDim.x + threadIdx.x;
    int total = K_ * din_p * outd;
    if (idx >= total) return;
    int o = idx % outd;
    int row = idx / outd;
    int k = row / din_p;
    int f = row - k * din_p;
    dst[idx] = (f < din_r) ? __float2half_rn(src[(size_t)(k * din_r + f) * outd + o])
                           : __float2half_rn(0.f);
}

// ------------------------------ data movement -------------------------------

// x (B,T,N,C) -> g_xT (T,N,B,C)
__global__ void k_transpose_x(const float* __restrict__ x) {
    int idx = blockIdx.x * blockDim.x + threadIdx.x;
    const int total = B_ * T_ * N_ * C_;
    if (idx >= total) return;
    int c = idx % C_;
    int i = (idx / C_) % N_;
    int t = (idx / (C_ * N_)) % T_;
    int b = idx / (C_ * N_ * T_);
    g_xT[(((size_t)t * N_ + i) * B_ + b) * C_ + c] = x[idx];
}

// Gate-pass concat: X[i][f][b] = concat(x,h), f < din_r, fp16-rounded.
__global__ void k_concat_full(const float* __restrict__ xin, int dinx,
                              const float* __restrict__ h,
                              __half* __restrict__ X, int din_r, int din_p) {
    int idx = blockIdx.x * blockDim.x + threadIdx.x;
    int total = N_ * din_r * B_;
    if (idx >= total) return;
    int b = idx & 63;
    int f = (idx >> 6) % din_r;
    int i = idx / (64 * din_r);
    int m = i * B_ + b;
    float v;
    if (f < dinx) v = xin[(size_t)m * dinx + f];
    else          v = h ? h[(size_t)m * H_ + (f - dinx)] : 0.f;
    X[((size_t)i * din_p + f) * B_ + b] = __float2half_rn(v);
}

// Candidate-pass concat: overwrite h-part with r*h.
__global__ void k_concat_h(const float* __restrict__ h, int dinx,
                           __half* __restrict__ X, int din_p) {
    int idx = blockIdx.x * blockDim.x + threadIdx.x;
    int total = N_ * H_ * B_;
    if (idx >= total) return;
    int b = idx & 63;
    int j = (idx >> 6) & 63;
    int i = idx >> 12;
    int m = i * B_ + b;
    float v = 0.f;
    if (h) v = h[(size_t)m * H_ + j] * g_zr[(size_t)m * (2 * H_) + H_ + j];
    X[((size_t)i * din_p + (dinx + j)) * B_ + b] = __float2half_rn(v);
}

// ------------------------------ stage-1 GEMM --------------------------------
// Y[s] = G[s] @ X over columns [col_off, col_off + gridX*128).
// BM=128, BN=128, BK=64, 8 warps (4x2), warp tile 32x64, fp16 mma m16n8k16.
// 2-stage cp.async double buffering in DYNAMIC smem; 16 K-iterations.
#define G1_A_ROWS 128
#define G1_A_LD   72
#define G1_B_ROWS 64
#define G1_B_LD   136
#define G1_A_BYTES (G1_A_ROWS * G1_A_LD * 2)          // 18432 per stage
#define G1_B_BYTES (G1_B_ROWS * G1_B_LD * 2)          // 17408 per stage
#define G1_SMEM (2 * (G1_A_BYTES + G1_B_BYTES))       // 71680

__global__ __launch_bounds__(256)
void k_gemm1(const __half* __restrict__ Gt, const __half* __restrict__ X,
             __half* __restrict__ Y, int col_off, int ldp) {
    extern __shared__ __align__(16) char dsm[];
    __half (*As)[G1_A_ROWS][G1_A_LD] =
        reinterpret_cast<__half(*)[G1_A_ROWS][G1_A_LD]>(dsm);
    __half (*Bs)[G1_B_ROWS][G1_B_LD] =
        reinterpret_cast<__half(*)[G1_B_ROWS][G1_B_LD]>(dsm + 2 * G1_A_BYTES);

    const int s = blockIdx.z;
    const __half* A = Gt + (size_t)s * N_ * N_;
    const int m0 = blockIdx.y * 128;
    const int n0 = col_off + blockIdx.x * 128;
    const int tid = threadIdx.x;
    const int lane = tid & 31;
    const int warp = tid >> 5;
    const int wm = (warp & 3) * 32;
    const int wn = (warp >> 2) * 64;
    const int gq = lane >> 2;
    const int t4 = lane & 3;

    float acc[2][8][4];
#pragma unroll
    for (int i = 0; i < 2; i++)
#pragma unroll
        for (int j = 0; j < 8; j++)
#pragma unroll
            for (int l = 0; l < 4; l++) acc[i][j][l] = 0.f;

    auto load_stage = [&](int buf, int kk0) {
        // A tile 128x64 halves = 16KB = 1024 cp16 (4/thread)
#pragma unroll
        for (int i = 0; i < 4; i++) {
            int idx = tid + i * 256;
            int row = idx >> 3;
            int seg = (idx & 7) << 3;
            cp16cg(&As[buf][row][seg], A + (size_t)(m0 + row) * N_ + kk0 + seg);
        }
        // B tile 64x128 halves = 16KB = 1024 cp16 (4/thread)
#pragma unroll
        for (int i = 0; i < 4; i++) {
            int idx = tid + i * 256;
            int r = idx >> 4;
            int seg = (idx & 15) << 3;
            cp16(&Bs[buf][r][seg], X + (size_t)(kk0 + r) * ldp + n0 + seg);
        }
    };

    load_stage(0, 0);
    cp_commit();

    const int KSTEPS = N_ / 64;   // 16
    for (int kt = 0; kt < KSTEPS; kt++) {
        int buf = kt & 1;
        if (kt + 1 < KSTEPS) {
            load_stage(buf ^ 1, (kt + 1) * 64);
            cp_commit();
            cp_wait<1>();
        } else {
            cp_wait<0>();
        }
        __syncthreads();

#pragma unroll
        for (int ks = 0; ks < 4; ks++) {
            const int kb = ks * 16;
            uint32_t a[2][4], b[8][2];
#pragma unroll
            for (int mt = 0; mt < 2; mt++) {
                ldmx4(a[mt], &As[buf][wm + mt * 16 + (lane & 15)]
                                     [kb + (lane >> 4) * 8]);
            }
#pragma unroll
            for (int p = 0; p < 4; p++) {
                uint32_t r[4];
                ldmx4t(r, &Bs[buf][kb + (lane & 7) + ((lane >> 3) & 1) * 8]
                                  [wn + p * 16 + (lane >> 4) * 8]);
                b[2 * p][0] = r[0]; b[2 * p][1] = r[1];
                b[2 * p + 1][0] = r[2]; b[2 * p + 1][1] = r[3];
            }
#pragma unroll
            for (int mt = 0; mt < 2; mt++)
#pragma unroll
                for (int nt = 0; nt < 8; nt++)
                    mma_f16(acc[mt][nt], a[mt], b[nt]);
        }
        __syncthreads();
    }

    // coalesced half2 stores
#pragma unroll
    for (int mt = 0; mt < 2; mt++) {
        int row = m0 + wm + mt * 16 + gq;
#pragma unroll
        for (int nt = 0; nt < 8; nt++) {
            int xcol = n0 + wn + nt * 8 + t4 * 2;
#pragma unroll
            for (int hh = 0; hh < 2; hh++) {
                int rr = row + hh * 8;
                __half2 v = __floats2half2_rn(acc[mt][nt][hh * 2 + 0],
                                              acc[mt][nt][hh * 2 + 1]);
                *(__half2*)&Y[((size_t)s * N_ + rr) * ldp + xcol] = v;
            }
        }
    }
}

// ------------------------- stage-2 gate GEMM (BN=128) ------------------------
// g_zr = sigmoid(A @ Wg + bg). A rows m=(node,b), cols (k,f) padded.
// BM=128, BN=128 (full gate width), BK=32, 8 warps (4x2), warp tile 32x64.
__global__ __launch_bounds__(256)
void k_gemm2g(const __half* __restrict__ Xp, const __half* __restrict__ Yp,
              const __half* __restrict__ W, const float* __restrict__ bias,
              int din_p) {
    __shared__ __align__(16) __half Ask[2][32][136];  // [k][m]
    __shared__ __align__(16) __half Bs[2][32][136];   // [k][n], n=128 + pad

    const int m0 = blockIdx.y * 128;
    const int i0 = m0 >> 6;
    const int tid = threadIdx.x;
    const int lane = tid & 31;
    const int warp = tid >> 5;
    const int wm = (warp & 3) * 32;
    const int wn = (warp >> 2) * 64;
    const int gq = lane >> 2;
    const int t4 = lane & 3;
    const int ldp = din_p * B_;

    float acc[2][8][4];
#pragma unroll
    for (int i = 0; i < 2; i++)
#pragma unroll
        for (int j = 0; j < 8; j++)
#pragma unroll
            for (int l = 0; l < 4; l++) acc[i][j][l] = 0.f;

    auto load_stage = [&](int buf, int kt) {
#pragma unroll
        for (int s16 = 0; s16 < 2; s16++) {
            int kk16 = kt * 32 + s16 * 16;
            int k = kk16 / din_p;
            int f0 = kk16 - k * din_p;
            const __half* basep;
            if (k == 0 || k == 3) basep = Xp;
            else basep = Yp + (size_t)((k < 3) ? k - 1 : k - 2) * N_ * ldp;
            int j = tid >> 4;
            int q = tid & 15;
            int node = q >> 3;
            int ch = (q & 7) << 3;
            cp16(&Ask[buf][s16 * 16 + j][node * 64 + ch],
                 basep + ((size_t)(i0 + node) * din_p + f0 + j) * B_ + ch);
        }
        // W tile 32x128 halves = 512 cp16 (2/thread)
        {
            int kk0 = kt * 32;
#pragma unroll
            for (int i = 0; i < 2; i++) {
                int idx = tid + i * 256;
                int r = idx >> 4;
                int ch = (idx & 15) << 3;
                cp16(&Bs[buf][r][ch], W + (size_t)(kk0 + r) * 128 + ch);
            }
        }
    };

    load_stage(0, 0);
    cp_commit();

    const int KSTEPS = (K_ * din_p) >> 5;
    for (int kt = 0; kt < KSTEPS; kt++) {
        int buf = kt & 1;
        if (kt + 1 < KSTEPS) {
            load_stage(buf ^ 1, kt + 1);
            cp_commit();
            cp_wait<1>();
        } else {
            cp_wait<0>();
        }
        __syncthreads();

#pragma unroll
        for (int ks = 0; ks < 2; ks++) {
            const int kb = ks * 16;
            uint32_t a[2][4], b[8][2];
#pragma unroll
            for (int mt = 0; mt < 2; mt++) {
                ldmx4t(a[mt], &Ask[buf][kb + (lane & 7) + ((lane >> 4) & 1) * 8]
                                       [wm + mt * 16 + ((lane >> 3) & 1) * 8]);
            }
#pragma unroll
            for (int p = 0; p < 4; p++) {
                uint32_t r[4];
                ldmx4t(r, &Bs[buf][kb + (lane & 7) + ((lane >> 3) & 1) * 8]
                                  [wn + p * 16 + (lane >> 4) * 8]);
                b[2 * p][0] = r[0]; b[2 * p][1] = r[1];
                b[2 * p + 1][0] = r[2]; b[2 * p + 1][1] = r[3];
            }
#pragma unroll
            for (int mt = 0; mt < 2; mt++)
#pragma unroll
                for (int nt = 0; nt < 8; nt++)
                    mma_f16(acc[mt][nt], a[mt], b[nt]);
        }
        __syncthreads();
    }

#pragma unroll
    for (int mt = 0; mt < 2; mt++) {
        int row = m0 + wm + mt * 16 + gq;
#pragma unroll
        for (int nt = 0; nt < 8; nt++) {
            int nb = wn + nt * 8 + t4 * 2;
#pragma unroll
            for (int hh = 0; hh < 2; hh++) {
                size_t m = (size_t)(row + hh * 8);
#pragma unroll
                for (int cc = 0; cc < 2; cc++) {
                    int n = nb + cc;
                    float v = acc[mt][nt][hh * 2 + cc] + bias[n];
                    g_zr[m * (2 * H_) + n] = 1.f / (1.f + expf(-v));
                }
            }
        }
    }
}

// ------------------------- stage-2 update GEMM (BN=64) -----------------------
// hout = z*tanh(A @ Wu + bu) + (1-z)*hprev.
// BM=128, BN=64, BK=32, 8 warps (4x2), warp tile 32x32. 2-stage cp.async.
__global__ __launch_bounds__(256)
void k_gemm2(const __half* __restrict__ Xp, const __half* __restrict__ Yp,
             const __half* __restrict__ W, const float* __restrict__ bias,
             int din_p,
             const float* __restrict__ hprev, float* __restrict__ hout) {
    __shared__ __align__(16) __half Ask[2][32][136];
    __shared__ __align__(16) __half Bs[2][32][72];

    const int m0 = blockIdx.y * 128;
    const int i0 = m0 >> 6;
    const int tid = threadIdx.x;
    const int lane = tid & 31;
    const int warp = tid >> 5;
    const int wm = (warp & 3) * 32;
    const int wn = (warp >> 2) * 32;
    const int gq = lane >> 2;
    const int t4 = lane & 3;
    const int ldp = din_p * B_;

    float acc[2][4][4];
#pragma unroll
    for (int i = 0; i < 2; i++)
#pragma unroll
        for (int j = 0; j < 4; j++)
#pragma unroll
            for (int l = 0; l < 4; l++) acc[i][j][l] = 0.f;

    auto load_stage = [&](int buf, int kt) {
#pragma unroll
        for (int s16 = 0; s16 < 2; s16++) {
            int kk16 = kt * 32 + s16 * 16;
            int k = kk16 / din_p;
            int f0 = kk16 - k * din_p;
            const __half* basep;
            if (k == 0 || k == 3) basep = Xp;
            else basep = Yp + (size_t)((k < 3) ? k - 1 : k - 2) * N_ * ldp;
            int j = tid >> 4;
            int q = tid & 15;
            int node = q >> 3;
            int ch = (q & 7) << 3;
            cp16(&Ask[buf][s16 * 16 + j][node * 64 + ch],
                 basep + ((size_t)(i0 + node) * din_p + f0 + j) * B_ + ch);
        }
        {
            int kk0 = kt * 32;
            int r = tid >> 3;
            int ch = (tid & 7) << 3;
            cp16(&Bs[buf][r][ch], W + (size_t)(kk0 + r) * 64 + ch);
        }
    };

    load_stage(0, 0);
    cp_commit();

    const int KSTEPS = (K_ * din_p) >> 5;
    for (int kt = 0; kt < KSTEPS; kt++) {
        int buf = kt & 1;
        if (kt + 1 < KSTEPS) {
            load_stage(buf ^ 1, kt + 1);
            cp_commit();
            cp_wait<1>();
        } else {
            cp_wait<0>();
        }
        __syncthreads();

#pragma unroll
        for (int ks = 0; ks < 2; ks++) {
            const int kb = ks * 16;
            uint32_t a[2][4], b[4][2];
#pragma unroll
            for (int mt = 0; mt < 2; mt++) {
                ldmx4t(a[mt], &Ask[buf][kb + (lane & 7) + ((lane >> 4) & 1) * 8]
                                       [wm + mt * 16 + ((lane >> 3) & 1) * 8]);
            }
#pragma unroll
            for (int p = 0; p < 2; p++) {
                uint32_t r[4];
                ldmx4t(r, &Bs[buf][kb + (lane & 7) + ((lane >> 3) & 1) * 8]
                                  [wn + p * 16 + (lane >> 4) * 8]);
                b[2 * p][0] = r[0]; b[2 * p][1] = r[1];
                b[2 * p + 1][0] = r[2]; b[2 * p + 1][1] = r[3];
            }
#pragma unroll
            for (int mt = 0; mt < 2; mt++)
#pragma unroll
                for (int nt = 0; nt < 4; nt++)
                    mma_f16(acc[mt][nt], a[mt], b[nt]);
        }
        __syncthreads();
    }

#pragma unroll
    for (int mt = 0; mt < 2; mt++) {
        int row = m0 + wm + mt * 16 + gq;
#pragma unroll
        for (int nt = 0; nt < 4; nt++) {
            int nb = wn + nt * 8 + t4 * 2;
#pragma unroll
            for (int hh = 0; hh < 2; hh++) {
                size_t m = (size_t)(row + hh * 8);
#pragma unroll
                for (int cc = 0; cc < 2; cc++) {
                    int n = nb + cc;
                    float v = acc[mt][nt][hh * 2 + cc] + bias[n];
                    float z = g_zr[m * (2 * H_) + n];
                    float hold = hprev ? hprev[m * H_ + n] : 0.f;
                    hout[m * H_ + n] = z * tanhf(v) + (1.f - z) * hold;
                }
            }
        }
    }
}

// Projection + output scatter + decoder feedback.
__global__ void k_proj(const float* __restrict__ projW,
                       const float* __restrict__ projb,
                       int t, float* __restrict__ out) {
    int m = blockIdx.x * blockDim.x + threadIdx.x;
    if (m >= M_) return;
    int i = m / B_;
    int b = m - i * B_;
    float a0 = projb[0], a1 = projb[1];
    const float* hv = &g_hB[(size_t)m * H_];
#pragma unroll
    for (int j = 0; j < H_; j++) {
        float h = hv[j];
        a0 += h * projW[j * 2 + 0];
        a1 += h * projW[j * 2 + 1];
    }
    g_y[(size_t)m * C_ + 0] = a0;
    g_y[(size_t)m * C_ + 1] = a1;
    size_t o = ((((size_t)b * HOR_ + t) * N_) + i) * C_;
    out[o + 0] = a0;
    out[o + 1] = a1;
}

// ------------------------------ host side -----------------------------------

static inline int cdiv(int a, int b) { return (a + b - 1) / b; }

// padded weight offsets inside g_Wp (element counts)
#define OFF_E0G 0
#define OFF_E0U 61440
#define OFF_D0G 92160
#define OFF_D0U 153600
#define OFF_E1G 184320
#define OFF_E1U 282624
#define OFF_D1G 331776
#define OFF_D1U 430080

static void cell_gate_start(const __half* Gt, const float* xin, int dinx,
                            const float* hprev, __half* Xp, __half* Yp,
                            int din_r, int din_p) {
    const int ldp = din_p * B_;
    k_concat_full<<<cdiv(N_ * din_r * B_, 256), 256>>>(xin, dinx, hprev,
                                                       Xp, din_r, din_p);
    dim3 g1((din_r * B_) / 128, N_ / 128, 4);
    k_gemm1<<<g1, 256, G1_SMEM>>>(Gt, Xp, Yp, 0, ldp);
}

static void cell_rest(const __half* Gt, int dinx,
                      const float* hprev, float* hout,
                      const __half* Wg, const float* bg,
                      const __half* Wu, const float* bu,
                      __half* Xp, __half* Yp, int din_p) {
    const int ldp = din_p * B_;
    k_gemm2g<<<dim3(1, M_ / 128), 256>>>(Xp, Yp, Wg, bg, din_p);
    k_concat_h<<<cdiv(N_ * H_ * B_, 256), 256>>>(hprev, dinx, Xp, din_p);
    dim3 g1h((H_ * B_) / 128, N_ / 128, 4);
    k_gemm1<<<g1h, 256, G1_SMEM>>>(Gt, Xp, Yp, dinx * B_, ldp);
    k_gemm2<<<dim3(1, M_ / 128), 256>>>(Xp, Yp, Wu, bu, din_p, hprev, hout);
}

static void run_cell(const __half* Gt, const float* xin, int dinx,
                     const float* hprev, float* hout,
                     const __half* Wg, const float* bg,
                     const __half* Wu, const float* bu,
                     __half* Xp, __half* Yp, int din_r, int din_p) {
    cell_gate_start(Gt, xin, dinx, hprev, Xp, Yp, din_r, din_p);
    cell_rest(Gt, dinx, hprev, hout, Wg, bg, Wu, bu, Xp, Yp, din_p);
}

extern "C" void kernel_launch(void* const* d_in, const int* in_sizes, int n_in,
                              void* d_out, int out_size) {
    (void)in_sizes; (void)n_in; (void)out_size;

    const float* x = (const float*)d_in[0];
    const float* G = (const float*)d_in[1];
    const float* w[16];
    for (int i = 0; i < 16; i++) w[i] = (const float*)d_in[2 + i];
    const float* projW = (const float*)d_in[18];
    const float* projb = (const float*)d_in[19];
    float* out = (float*)d_out;

    cudaFuncSetAttribute(k_gemm1, cudaFuncAttributeMaxDynamicSharedMemorySize,
                         G1_SMEM);

    float *p_xT, *p_seq, *p_hA, *p_hB, *p_y;
    __half *p_X0, *p_X1, *p_Y0, *p_Y1, *p_Gt, *p_Wp;
    cudaGetSymbolAddress((void**)&p_xT,  g_xT);
    cudaGetSymbolAddress((void**)&p_seq, g_seq);
    cudaGetSymbolAddress((void**)&p_hA,  g_hA);
    cudaGetSymbolAddress((void**)&p_hB,  g_hB);
    cudaGetSymbolAddress((void**)&p_y,   g_y);
    cudaGetSymbolAddress((void**)&p_X0,  g_X0);
    cudaGetSymbolAddress((void**)&p_X1,  g_X1);
    cudaGetSymbolAddress((void**)&p_Y0,  g_Y0);
    cudaGetSymbolAddress((void**)&p_Y1,  g_Y1);
    cudaGetSymbolAddress((void**)&p_Gt,  g_Gt);
    cudaGetSymbolAddress((void**)&p_Wp,  g_Wp);

    // prep
    k_prep_G<<<cdiv(4 * N_ * N_, 256), 256>>>(G);
    {
        int total = B_ * T_ * N_ * C_;
        k_transpose_x<<<cdiv(total, 256), 256>>>(x);
    }
    k_prep_W<<<cdiv(K_ * DINP0 * 128, 256), 256>>>(w[0], p_Wp + OFF_E0G,
                                                   DINR0, DINP0, 128);
    k_prep_W<<<cdiv(K_ * DINP0 *  64, 256), 256>>>(w[2], p_Wp + OFF_E0U,
                                                   DINR0, DINP0,  64);
    // enc0 t=0 gate pass start
    cell_gate_start(p_Gt, p_xT, C_, nullptr, p_X0, p_Y0, DINR0, DINP0);

    // remaining weight prep (stream-ordered before first use)
    k_prep_W<<<cdiv(K_ * DINP1 * 128, 256), 256>>>(w[4],  p_Wp + OFF_E1G, DINR1, DINP1, 128);
    k_prep_W<<<cdiv(K_ * DINP1 *  64, 256), 256>>>(w[6],  p_Wp + OFF_E1U, DINR1, DINP1,  64);
    k_prep_W<<<cdiv(K_ * DINP0 * 128, 256), 256>>>(w[8],  p_Wp + OFF_D0G, DINR0, DINP0, 128);
    k_prep_W<<<cdiv(K_ * DINP0 *  64, 256), 256>>>(w[10], p_Wp + OFF_D0U, DINR0, DINP0,  64);
    k_prep_W<<<cdiv(K_ * DINP1 * 128, 256), 256>>>(w[12], p_Wp + OFF_D1G, DINR1, DINP1, 128);
    k_prep_W<<<cdiv(K_ * DINP1 *  64, 256), 256>>>(w[14], p_Wp + OFF_D1U, DINR1, DINP1,  64);

    // finish enc0 t=0
    cell_rest(p_Gt, C_, nullptr, p_seq,
              p_Wp + OFF_E0G, w[1], p_Wp + OFF_E0U, w[3],
              p_X0, p_Y0, DINP0);

    // encoder layer 0, t=1..11
    for (int t = 1; t < T_; t++) {
        const float* xin   = p_xT + (size_t)t * N_ * B_ * C_;
        const float* hprev = p_seq + (size_t)(t - 1) * NBH_;
        float* hout        = p_seq + (size_t)t * NBH_;
        run_cell(p_Gt, xin, C_, hprev, hout,
                 p_Wp + OFF_E0G, w[1], p_Wp + OFF_E0U, w[3],
                 p_X0, p_Y0, DINR0, DINP0);
    }

    // encoder layer 1 (din 128)
    for (int t = 0; t < T_; t++) {
        const float* xin   = p_seq + (size_t)t * NBH_;
        const float* hprev = (t == 0) ? nullptr : p_hB;
        run_cell(p_Gt, xin, H_, hprev, p_hB,
                 p_Wp + OFF_E1G, w[5], p_Wp + OFF_E1U, w[7],
                 p_X1, p_Y1, DINR1, DINP1);
    }

    // decoder feedback init
    cudaMemsetAsync(p_y, 0, (size_t)M_ * C_ * sizeof(float));

    // decoder loop
    for (int t = 0; t < HOR_; t++) {
        const float* h0prev = (t == 0) ? (p_seq + (size_t)(T_ - 1) * NBH_)
                                       : p_hA;
        run_cell(p_Gt, p_y, C_, h0prev, p_hA,
                 p_Wp + OFF_D0G, w[9], p_Wp + OFF_D0U, w[11],
                 p_X0, p_Y0, DINR0, DINP0);
        run_cell(p_Gt, p_hA, H_, p_hB, p_hB,
                 p_Wp + OFF_D1G, w[13], p_Wp + OFF_D1U, w[15],
                 p_X1, p_Y1, DINR1, DINP1);
        k_proj<<<cdiv(M_, 256), 256>>>(projW, projb, t, out);
    }
}